// round 2
// baseline (speedup 1.0000x reference)
#include <cuda_runtime.h>

// ---------------------------------------------------------------------------
// QuantumAttention: B=4, S=1024, E=1024, H=16, HD=64
// out  = [B,S,E]           -> d_out[0 .. 4194304)
// probs= [B,H,S,S] (mixed) -> d_out[4194304 .. 71303168)
// ---------------------------------------------------------------------------

#define Bc 4
#define Sc 1024
#define Ec 1024
#define Hc 16
#define HDc 64
#define Mc (Bc * Sc)           // 4096
#define OUT_OFF (Bc * Sc * Ec) // 4194304

// Scratch (device globals: allocation-free per harness rules)
__device__ float g_Wq_eff[Ec * Ec];
__device__ float g_Wk_eff[Ec * Ec];
__device__ float g_bq_eff[Ec];
__device__ float g_bk_eff[Ec];
__device__ float g_Q[Bc * Hc * Sc * HDc];
__device__ float g_K[Bc * Hc * Sc * HDc];
__device__ float g_V[Bc * Hc * Sc * HDc];
__device__ float g_ctx[Bc * Hc * Sc * HDc];
__device__ float g_rowsum[Bc * Hc * Sc];
__device__ float g_E[Bc * Hc * Sc * Sc];   // 256 MB: exp(scores), pre-normalization
__device__ int   g_partner[Hc];
__device__ float g_pw[Hc];

// ---------------------------------------------------------------------------
// Small setup: entanglement partners/weights + effective biases
// ---------------------------------------------------------------------------
__global__ void init_misc_kernel(const float* __restrict__ ent,
                                 const float* __restrict__ had,
                                 const float* __restrict__ phase,
                                 const float* __restrict__ bq,
                                 const float* __restrict__ bk) {
    int t = threadIdx.x;
    if (t < Hc) {
        int p = t; float w = 0.f;
        for (int h = 0; h < Hc; h++) {
            if (h != t && ent[h * Hc + t] != 0.f) { p = h; w = ent[h * Hc + t]; }
        }
        g_partner[t] = p;
        g_pw[t] = w;
    }
    for (int j = t; j < Ec; j += blockDim.x) {
        int h = j >> 6, e = j & 63;
        float aq = 0.f, ak = 0.f;
        for (int d = 0; d < HDc; d++) {
            float hv = had[d * HDc + e];
            aq += hv * bq[h * HDc + d];
            ak += hv * bk[h * HDc + d];
        }
        float c = cosf(phase[j]);
        g_bq_eff[j] = c * aq;
        g_bk_eff[j] = c * ak;
    }
}

__global__ void zero_rowsum_kernel() {
    int i = blockIdx.x * blockDim.x + threadIdx.x;
    if (i < Bc * Hc * Sc) g_rowsum[i] = 0.f;
}

// ---------------------------------------------------------------------------
// Weight transform: Weff[h*64+e', i] = cos(phase[h,e']) * sum_d had[d,e'] * W[h*64+d, i]
// grid: (H, E/16), 256 threads
// ---------------------------------------------------------------------------
__global__ void wtrans_kernel(const float* __restrict__ W,
                              const float* __restrict__ had,
                              const float* __restrict__ phase,
                              int which) {
    float* Weff = (which == 0) ? g_Wq_eff : g_Wk_eff;
    __shared__ float sH[HDc * HDc];
    __shared__ float sW[HDc][17];
    __shared__ float sc[HDc];
    int h = blockIdx.x;
    int i0 = blockIdx.y * 16;
    int t = threadIdx.x;
    for (int j = t; j < HDc * HDc; j += 256) sH[j] = had[j];
    if (t < HDc) sc[t] = cosf(phase[h * HDc + t]);
    for (int j = t; j < HDc * 16; j += 256) {
        int d = j >> 4, ii = j & 15;
        sW[d][ii] = W[(h * HDc + d) * Ec + i0 + ii];
    }
    __syncthreads();
#pragma unroll
    for (int oo = 0; oo < 4; oo++) {
        int j = t * 4 + oo;
        int e = j >> 4, ii = j & 15;
        float acc = 0.f;
#pragma unroll
        for (int d = 0; d < HDc; d++) acc += sH[d * HDc + e] * sW[d][ii];
        Weff[(h * HDc + e) * Ec + i0 + ii] = sc[e] * acc;
    }
}

// ---------------------------------------------------------------------------
// Projection SGEMM: C[4096,1024] = A @ W^T + bias -> head layout [b,h,s,d]
// 128x128 CTA tile, 16 k-tile, 8x8 microtile (split 4+4 for conflict-free LDS.128)
// grid: (1024/128, 4096/128) = (8, 32)
// ---------------------------------------------------------------------------
__global__ __launch_bounds__(256) void sgemm_proj_kernel(
    const float* __restrict__ A, const float* __restrict__ Wraw,
    const float* __restrict__ braw, int which) {
    const float* W    = (which == 0) ? g_Wq_eff : (which == 1) ? g_Wk_eff : Wraw;
    const float* bias = (which == 0) ? g_bq_eff : (which == 1) ? g_bk_eff : braw;
    float* Out        = (which == 0) ? g_Q : (which == 1) ? g_K : g_V;

    __shared__ float As[16][132];
    __shared__ float Ws[16][132];
    const int t = threadIdx.x;
    const int tx = t & 15, ty = t >> 4;
    const int m0 = blockIdx.y * 128;
    const int n0 = blockIdx.x * 128;

    float acc[8][8];
#pragma unroll
    for (int i = 0; i < 8; i++)
#pragma unroll
        for (int j = 0; j < 8; j++) acc[i][j] = 0.f;

    for (int k0 = 0; k0 < Ec; k0 += 16) {
#pragma unroll
        for (int l = 0; l < 2; l++) {
            int f = t * 2 + l;
            int row = f >> 2, kq = (f & 3) * 4;
            float4 va = *(const float4*)&A[(m0 + row) * Ec + k0 + kq];
            As[kq + 0][row] = va.x; As[kq + 1][row] = va.y;
            As[kq + 2][row] = va.z; As[kq + 3][row] = va.w;
            float4 vw = *(const float4*)&W[(n0 + row) * Ec + k0 + kq];
            Ws[kq + 0][row] = vw.x; Ws[kq + 1][row] = vw.y;
            Ws[kq + 2][row] = vw.z; Ws[kq + 3][row] = vw.w;
        }
        __syncthreads();
#pragma unroll
        for (int kk = 0; kk < 16; kk++) {
            float4 a0 = *(const float4*)&As[kk][ty * 4];
            float4 a1 = *(const float4*)&As[kk][64 + ty * 4];
            float4 b0 = *(const float4*)&Ws[kk][tx * 4];
            float4 b1 = *(const float4*)&Ws[kk][64 + tx * 4];
            float av[8] = {a0.x, a0.y, a0.z, a0.w, a1.x, a1.y, a1.z, a1.w};
            float bv[8] = {b0.x, b0.y, b0.z, b0.w, b1.x, b1.y, b1.z, b1.w};
#pragma unroll
            for (int i = 0; i < 8; i++)
#pragma unroll
                for (int j = 0; j < 8; j++) acc[i][j] += av[i] * bv[j];
        }
        __syncthreads();
    }

    const int h0 = n0 >> 6;
    float4 bb0 = *(const float4*)&bias[n0 + tx * 4];
    float4 bb1 = *(const float4*)&bias[n0 + 64 + tx * 4];
#pragma unroll
    for (int i = 0; i < 8; i++) {
        int r = (i < 4) ? (ty * 4 + i) : (64 + ty * 4 + i - 4);
        int m = m0 + r;
        int b = m >> 10, s = m & 1023;
        float4 o0 = make_float4(acc[i][0] + bb0.x, acc[i][1] + bb0.y,
                                acc[i][2] + bb0.z, acc[i][3] + bb0.w);
        float4 o1 = make_float4(acc[i][4] + bb1.x, acc[i][5] + bb1.y,
                                acc[i][6] + bb1.z, acc[i][7] + bb1.w);
        *(float4*)&Out[((b * Hc + h0) * Sc + s) * HDc + tx * 4] = o0;
        *(float4*)&Out[((b * Hc + h0 + 1) * Sc + s) * HDc + tx * 4] = o1;
    }
}

// ---------------------------------------------------------------------------
// Scores: E = exp(Q K^T / 8), accumulate row sums. Per (b,h): 1024x1024, K=64.
// grid: (8, 8, 64), 256 threads
// ---------------------------------------------------------------------------
__global__ __launch_bounds__(256) void scores_kernel() {
    __shared__ float As[16][132];
    __shared__ float Ws[16][132];
    __shared__ float rs[128];
    const int t = threadIdx.x;
    const int tx = t & 15, ty = t >> 4;
    const int bh = blockIdx.z;
    const int m0 = blockIdx.y * 128;
    const int n0 = blockIdx.x * 128;
    const float* Qb = g_Q + bh * Sc * HDc;
    const float* Kb = g_K + bh * Sc * HDc;

    float acc[8][8];
#pragma unroll
    for (int i = 0; i < 8; i++)
#pragma unroll
        for (int j = 0; j < 8; j++) acc[i][j] = 0.f;

    for (int k0 = 0; k0 < HDc; k0 += 16) {
#pragma unroll
        for (int l = 0; l < 2; l++) {
            int f = t * 2 + l;
            int row = f >> 2, kq = (f & 3) * 4;
            float4 va = *(const float4*)&Qb[(m0 + row) * HDc + k0 + kq];
            As[kq + 0][row] = va.x; As[kq + 1][row] = va.y;
            As[kq + 2][row] = va.z; As[kq + 3][row] = va.w;
            float4 vw = *(const float4*)&Kb[(n0 + row) * HDc + k0 + kq];
            Ws[kq + 0][row] = vw.x; Ws[kq + 1][row] = vw.y;
            Ws[kq + 2][row] = vw.z; Ws[kq + 3][row] = vw.w;
        }
        __syncthreads();
#pragma unroll
        for (int kk = 0; kk < 16; kk++) {
            float4 a0 = *(const float4*)&As[kk][ty * 4];
            float4 a1 = *(const float4*)&As[kk][64 + ty * 4];
            float4 b0 = *(const float4*)&Ws[kk][tx * 4];
            float4 b1 = *(const float4*)&Ws[kk][64 + tx * 4];
            float av[8] = {a0.x, a0.y, a0.z, a0.w, a1.x, a1.y, a1.z, a1.w};
            float bv[8] = {b0.x, b0.y, b0.z, b0.w, b1.x, b1.y, b1.z, b1.w};
#pragma unroll
            for (int i = 0; i < 8; i++)
#pragma unroll
                for (int j = 0; j < 8; j++) acc[i][j] += av[i] * bv[j];
        }
        __syncthreads();
    }

    if (t < 128) rs[t] = 0.f;
    __syncthreads();

    float* Eb = g_E + bh * Sc * Sc;
#pragma unroll
    for (int i = 0; i < 8; i++) {
        int r = (i < 4) ? (ty * 4 + i) : (64 + ty * 4 + i - 4);
        float e[8];
#pragma unroll
        for (int j = 0; j < 8; j++) e[j] = __expf(acc[i][j] * 0.125f);
        float4 o0 = make_float4(e[0], e[1], e[2], e[3]);
        float4 o1 = make_float4(e[4], e[5], e[6], e[7]);
        *(float4*)&Eb[(m0 + r) * Sc + n0 + tx * 4] = o0;
        *(float4*)&Eb[(m0 + r) * Sc + n0 + 64 + tx * 4] = o1;
        float rsum = e[0] + e[1] + e[2] + e[3] + e[4] + e[5] + e[6] + e[7];
        atomicAdd(&rs[r], rsum);
    }
    __syncthreads();
    if (t < 128) atomicAdd(&g_rowsum[bh * Sc + m0 + t], rs[t]);
}

// ---------------------------------------------------------------------------
// Fused normalize + entanglement mix + probs write + ctx = P @ V
// Per CTA: (b, head g, 128 q rows) -> mixed probs [128,1024] out, ctx [128,64]
// grid: (8, 64), 256 threads
// ---------------------------------------------------------------------------
__global__ __launch_bounds__(256) void mixctx_kernel(float* __restrict__ Pout) {
    __shared__ float Ps[16][132];
    __shared__ float Vs[16][68];
    __shared__ float ivg[128];
    __shared__ float ivp[128];
    const int t = threadIdx.x;
    const int tx = t & 15, ty = t >> 4;
    const int bh = blockIdx.y;
    const int b = bh >> 4, g = bh & 15;
    const int q0 = blockIdx.x * 128;
    const int p = g_partner[g];
    const float w = g_pw[g];

    if (t < 128) {
        ivg[t] = 1.f / g_rowsum[(b * Hc + g) * Sc + q0 + t];
        ivp[t] = w / g_rowsum[(b * Hc + p) * Sc + q0 + t];
    }
    const float* Eg = g_E + (b * Hc + g) * Sc * Sc;
    const float* Ep = g_E + (b * Hc + p) * Sc * Sc;
    const float* Vb = g_V + (b * Hc + g) * Sc * HDc;
    float* Pg = Pout + (size_t)(b * Hc + g) * Sc * Sc;

    float acc[8][4];
#pragma unroll
    for (int i = 0; i < 8; i++)
#pragma unroll
        for (int j = 0; j < 4; j++) acc[i][j] = 0.f;

    __syncthreads();

    for (int kt = 0; kt < Sc; kt += 16) {
#pragma unroll
        for (int l = 0; l < 2; l++) {
            int f = t * 2 + l;
            int row = f >> 2, kq = (f & 3) * 4;
            int q = q0 + row;
            int k = kt + kq;
            float4 eg = *(const float4*)&Eg[q * Sc + k];
            float4 ep = *(const float4*)&Ep[q * Sc + k];
            float ig = ivg[row], ip = ivp[row];
            float4 pr = make_float4(eg.x * ig + ep.x * ip, eg.y * ig + ep.y * ip,
                                    eg.z * ig + ep.z * ip, eg.w * ig + ep.w * ip);
            *(float4*)&Pg[q * Sc + k] = pr;
            Ps[kq + 0][row] = pr.x; Ps[kq + 1][row] = pr.y;
            Ps[kq + 2][row] = pr.z; Ps[kq + 3][row] = pr.w;
        }
        {
            int row = t >> 4;
            int dq = (t & 15) * 4;
            *(float4*)&Vs[row][dq] = *(const float4*)&Vb[(kt + row) * HDc + dq];
        }
        __syncthreads();
#pragma unroll
        for (int kk = 0; kk < 16; kk++) {
            float4 a0 = *(const float4*)&Ps[kk][ty * 4];
            float4 a1 = *(const float4*)&Ps[kk][64 + ty * 4];
            float4 bv = *(const float4*)&Vs[kk][tx * 4];
            float av[8] = {a0.x, a0.y, a0.z, a0.w, a1.x, a1.y, a1.z, a1.w};
            float bb[4] = {bv.x, bv.y, bv.z, bv.w};
#pragma unroll
            for (int i = 0; i < 8; i++)
#pragma unroll
                for (int j = 0; j < 4; j++) acc[i][j] += av[i] * bb[j];
        }
        __syncthreads();
    }

#pragma unroll
    for (int i = 0; i < 8; i++) {
        int r = (i < 4) ? (ty * 4 + i) : (64 + ty * 4 + i - 4);
        float4 o = make_float4(acc[i][0], acc[i][1], acc[i][2], acc[i][3]);
        *(float4*)&g_ctx[((b * Hc + g) * Sc + q0 + r) * HDc + tx * 4] = o;
    }
}

// ---------------------------------------------------------------------------
// Output projection: out[4096,1024] = ctx_flat @ Wo^T + bo
// ctx stored head-major; loader maps k -> (h = k/64, d = k%64)
// ---------------------------------------------------------------------------
__global__ __launch_bounds__(256) void sgemm_out_kernel(
    const float* __restrict__ W, const float* __restrict__ bias,
    float* __restrict__ Out) {
    __shared__ float As[16][132];
    __shared__ float Ws[16][132];
    const int t = threadIdx.x;
    const int tx = t & 15, ty = t >> 4;
    const int m0 = blockIdx.y * 128;
    const int n0 = blockIdx.x * 128;

    float acc[8][8];
#pragma unroll
    for (int i = 0; i < 8; i++)
#pragma unroll
        for (int j = 0; j < 8; j++) acc[i][j] = 0.f;

    for (int k0 = 0; k0 < Ec; k0 += 16) {
#pragma unroll
        for (int l = 0; l < 2; l++) {
            int f = t * 2 + l;
            int row = f >> 2, kq = (f & 3) * 4;
            int m = m0 + row;
            int b = m >> 10, s = m & 1023;
            int k = k0 + kq;
            float4 va = *(const float4*)&g_ctx[((b * Hc + (k >> 6)) * Sc + s) * HDc + (k & 63)];
            As[kq + 0][row] = va.x; As[kq + 1][row] = va.y;
            As[kq + 2][row] = va.z; As[kq + 3][row] = va.w;
            float4 vw = *(const float4*)&W[(n0 + row) * Ec + k];
            Ws[kq + 0][row] = vw.x; Ws[kq + 1][row] = vw.y;
            Ws[kq + 2][row] = vw.z; Ws[kq + 3][row] = vw.w;
        }
        __syncthreads();
#pragma unroll
        for (int kk = 0; kk < 16; kk++) {
            float4 a0 = *(const float4*)&As[kk][ty * 4];
            float4 a1 = *(const float4*)&As[kk][64 + ty * 4];
            float4 b0 = *(const float4*)&Ws[kk][tx * 4];
            float4 b1 = *(const float4*)&Ws[kk][64 + tx * 4];
            float av[8] = {a0.x, a0.y, a0.z, a0.w, a1.x, a1.y, a1.z, a1.w};
            float bv[8] = {b0.x, b0.y, b0.z, b0.w, b1.x, b1.y, b1.z, b1.w};
#pragma unroll
            for (int i = 0; i < 8; i++)
#pragma unroll
                for (int j = 0; j < 8; j++) acc[i][j] += av[i] * bv[j];
        }
        __syncthreads();
    }

    float4 bb0 = *(const float4*)&bias[n0 + tx * 4];
    float4 bb1 = *(const float4*)&bias[n0 + 64 + tx * 4];
#pragma unroll
    for (int i = 0; i < 8; i++) {
        int r = (i < 4) ? (ty * 4 + i) : (64 + ty * 4 + i - 4);
        int m = m0 + r;
        float4 o0 = make_float4(acc[i][0] + bb0.x, acc[i][1] + bb0.y,
                                acc[i][2] + bb0.z, acc[i][3] + bb0.w);
        float4 o1 = make_float4(acc[i][4] + bb1.x, acc[i][5] + bb1.y,
                                acc[i][6] + bb1.z, acc[i][7] + bb1.w);
        *(float4*)&Out[m * Ec + n0 + tx * 4] = o0;
        *(float4*)&Out[m * Ec + n0 + 64 + tx * 4] = o1;
    }
}

// ---------------------------------------------------------------------------
extern "C" void kernel_launch(void* const* d_in, const int* in_sizes, int n_in,
                              void* d_out, int out_size) {
    const float* query    = (const float*)d_in[0];
    const float* key      = (const float*)d_in[1];
    const float* value    = (const float*)d_in[2];
    const float* Wq       = (const float*)d_in[3];
    const float* bq       = (const float*)d_in[4];
    const float* Wk       = (const float*)d_in[5];
    const float* bk       = (const float*)d_in[6];
    const float* Wv       = (const float*)d_in[7];
    const float* bv       = (const float*)d_in[8];
    const float* Wo       = (const float*)d_in[9];
    const float* bo       = (const float*)d_in[10];
    const float* phase    = (const float*)d_in[11];
    const float* hadamard = (const float*)d_in[12];
    const float* ent      = (const float*)d_in[13];

    float* out   = (float*)d_out;
    float* probs = out + OUT_OFF;

    init_misc_kernel<<<1, 256>>>(ent, hadamard, phase, bq, bk);
    zero_rowsum_kernel<<<(Bc * Hc * Sc) / 256, 256>>>();
    wtrans_kernel<<<dim3(Hc, Ec / 16), 256>>>(Wq, hadamard, phase, 0);
    wtrans_kernel<<<dim3(Hc, Ec / 16), 256>>>(Wk, hadamard, phase, 1);

    dim3 gp(Ec / 128, Mc / 128);
    sgemm_proj_kernel<<<gp, 256>>>(query, nullptr, nullptr, 0);
    sgemm_proj_kernel<<<gp, 256>>>(key, nullptr, nullptr, 1);
    sgemm_proj_kernel<<<gp, 256>>>(value, Wv, bv, 2);

    scores_kernel<<<dim3(Sc / 128, Sc / 128, Bc * Hc), 256>>>();
    mixctx_kernel<<<dim3(Sc / 128, Bc * Hc), 256>>>(probs);
    sgemm_out_kernel<<<gp, 256>>>(Wo, bo, out);
}

// round 3
// speedup vs baseline: 1.6695x; 1.6695x over previous
#include <cuda_runtime.h>
#include <cstdint>

// ---------------------------------------------------------------------------
// QuantumAttention: B=4, S=1024, E=1024, H=16, HD=64
// out  = [B,S,E]           -> d_out[0 .. 4194304)
// probs= [B,H,S,S] (mixed) -> d_out[4194304 .. 71303168)
// Round 3: TF32 mma.sync tensor cores for all GEMM-shaped work.
// ---------------------------------------------------------------------------

#define Bc 4
#define Sc 1024
#define Ec 1024
#define Hc 16
#define HDc 64
#define Mc (Bc * Sc)           // 4096
#define OUT_OFF (Bc * Sc * Ec) // 4194304

// Scratch (device globals: allocation-free per harness rules)
__device__ float g_Wq_eff[Ec * Ec];
__device__ float g_Wk_eff[Ec * Ec];
__device__ float g_bq_eff[Ec];
__device__ float g_bk_eff[Ec];
__device__ float g_Q[Bc * Hc * Sc * HDc];
__device__ float g_K[Bc * Hc * Sc * HDc];
__device__ float g_V[Bc * Hc * Sc * HDc];
__device__ float g_ctx[Bc * Hc * Sc * HDc];
__device__ float g_rowsum[Bc * Hc * Sc];
__device__ float g_E[Bc * Hc * Sc * Sc];   // 256 MB: exp(scores), pre-normalization
__device__ int   g_partner[Hc];
__device__ float g_pw[Hc];

// ---------------------------------------------------------------------------
// TF32 helpers
// ---------------------------------------------------------------------------
__device__ __forceinline__ uint32_t f2tf32(float x) {
    uint32_t r;
    asm("cvt.rna.tf32.f32 %0, %1;" : "=r"(r) : "f"(x));
    return r;
}

__device__ __forceinline__ void mma_tf32(float* c, const uint32_t* a,
                                         uint32_t b0, uint32_t b1) {
    asm volatile(
        "mma.sync.aligned.m16n8k8.row.col.f32.tf32.tf32.f32 "
        "{%0,%1,%2,%3}, {%4,%5,%6,%7}, {%8,%9}, {%0,%1,%2,%3};\n"
        : "+f"(c[0]), "+f"(c[1]), "+f"(c[2]), "+f"(c[3])
        : "r"(a[0]), "r"(a[1]), "r"(a[2]), "r"(a[3]), "r"(b0), "r"(b1));
}

// ---------------------------------------------------------------------------
// Small setup: entanglement partners/weights + effective biases
// ---------------------------------------------------------------------------
__global__ void init_misc_kernel(const float* __restrict__ ent,
                                 const float* __restrict__ had,
                                 const float* __restrict__ phase,
                                 const float* __restrict__ bq,
                                 const float* __restrict__ bk) {
    int t = threadIdx.x;
    if (t < Hc) {
        int p = t; float w = 0.f;
        for (int h = 0; h < Hc; h++) {
            if (h != t && ent[h * Hc + t] != 0.f) { p = h; w = ent[h * Hc + t]; }
        }
        g_partner[t] = p;
        g_pw[t] = w;
    }
    for (int j = t; j < Ec; j += blockDim.x) {
        int h = j >> 6, e = j & 63;
        float aq = 0.f, ak = 0.f;
        for (int d = 0; d < HDc; d++) {
            float hv = had[d * HDc + e];
            aq += hv * bq[h * HDc + d];
            ak += hv * bk[h * HDc + d];
        }
        float c = cosf(phase[j]);
        g_bq_eff[j] = c * aq;
        g_bk_eff[j] = c * ak;
    }
}

__global__ void zero_rowsum_kernel() {
    int i = blockIdx.x * blockDim.x + threadIdx.x;
    if (i < Bc * Hc * Sc) g_rowsum[i] = 0.f;
}

// ---------------------------------------------------------------------------
// Weight transform: Weff[h*64+e, i] = cos(phase[h,e]) * sum_d had[d,e] * W[h*64+d, i]
// grid: (16, 16) = (h, 64-col chunk). 4e x 4i register tiling.
// ---------------------------------------------------------------------------
__global__ __launch_bounds__(256) void wtrans_kernel(const float* __restrict__ W,
                                                     const float* __restrict__ had,
                                                     const float* __restrict__ phase,
                                                     int which) {
    float* Weff = (which == 0) ? g_Wq_eff : g_Wk_eff;
    __shared__ float sH[HDc * 65];
    __shared__ float sW[HDc][68];
    __shared__ float sc[HDc];
    const int h = blockIdx.x;
    const int i0 = blockIdx.y * 64;
    const int t = threadIdx.x;
    for (int j = t; j < HDc * HDc; j += 256) {
        int d = j >> 6, e = j & 63;
        sH[d * 65 + e] = had[j];
    }
    if (t < HDc) sc[t] = cosf(phase[h * HDc + t]);
#pragma unroll
    for (int i = 0; i < 4; i++) {
        int idx = i * 256 + t;
        int d = idx >> 4, q = (idx & 15) * 4;
        *(float4*)&sW[d][q] = *(const float4*)&W[(h * HDc + d) * Ec + i0 + q];
    }
    __syncthreads();

    const int tx = t & 15;       // 16 i-groups of 4
    const int ty = t >> 4;       // 16 e-groups of 4
    float acc[4][4];
#pragma unroll
    for (int a = 0; a < 4; a++)
#pragma unroll
        for (int b = 0; b < 4; b++) acc[a][b] = 0.f;

#pragma unroll 8
    for (int d = 0; d < HDc; d++) {
        float4 w = *(const float4*)&sW[d][tx * 4];
#pragma unroll
        for (int ee = 0; ee < 4; ee++) {
            float hv = sH[d * 65 + ty * 4 + ee];
            acc[ee][0] += hv * w.x;
            acc[ee][1] += hv * w.y;
            acc[ee][2] += hv * w.z;
            acc[ee][3] += hv * w.w;
        }
    }
#pragma unroll
    for (int ee = 0; ee < 4; ee++) {
        int e = ty * 4 + ee;
        float s = sc[e];
        float4 o = make_float4(s * acc[ee][0], s * acc[ee][1],
                               s * acc[ee][2], s * acc[ee][3]);
        *(float4*)&Weff[(h * HDc + e) * Ec + i0 + tx * 4] = o;
    }
}

// ---------------------------------------------------------------------------
// TF32 projection GEMM: C[4096,1024] = A @ W^T + bias -> head layout [b,h,s,d]
// 128x128 CTA, k-tile 32, 8 warps (4m x 2n), warp tile 32x64, mma m16n8k8.
// grid: (8, 32)
// ---------------------------------------------------------------------------
__global__ __launch_bounds__(256) void gemm_tf32_proj(
    const float* __restrict__ A, const float* __restrict__ Wraw,
    const float* __restrict__ braw, int which) {
    const float* W    = (which == 0) ? g_Wq_eff : (which == 1) ? g_Wk_eff : Wraw;
    const float* bias = (which == 0) ? g_bq_eff : (which == 1) ? g_bk_eff : braw;
    float* Out        = (which == 0) ? g_Q : (which == 1) ? g_K : g_V;

    __shared__ uint32_t As[32][133];
    __shared__ uint32_t Bs[32][133];
    const int t = threadIdx.x;
    const int lane = t & 31, warp = t >> 5;
    const int gid = lane >> 2, tig = lane & 3;
    const int wm = (warp & 3) * 32, wn = (warp >> 2) * 64;
    const int m0 = blockIdx.y * 128, n0 = blockIdx.x * 128;

    float acc[2][8][4];
#pragma unroll
    for (int mi = 0; mi < 2; mi++)
#pragma unroll
        for (int ni = 0; ni < 8; ni++)
#pragma unroll
            for (int j = 0; j < 4; j++) acc[mi][ni][j] = 0.f;

    for (int k0 = 0; k0 < Ec; k0 += 32) {
#pragma unroll
        for (int i = 0; i < 4; i++) {
            int idx = i * 256 + t;
            int row = idx >> 3, kq = (idx & 7) * 4;
            float4 va = *(const float4*)&A[(m0 + row) * Ec + k0 + kq];
            As[kq + 0][row] = f2tf32(va.x); As[kq + 1][row] = f2tf32(va.y);
            As[kq + 2][row] = f2tf32(va.z); As[kq + 3][row] = f2tf32(va.w);
            float4 vb = *(const float4*)&W[(n0 + row) * Ec + k0 + kq];
            Bs[kq + 0][row] = f2tf32(vb.x); Bs[kq + 1][row] = f2tf32(vb.y);
            Bs[kq + 2][row] = f2tf32(vb.z); Bs[kq + 3][row] = f2tf32(vb.w);
        }
        __syncthreads();
#pragma unroll
        for (int ks = 0; ks < 4; ks++) {
            int kb = ks * 8;
            uint32_t a[2][4];
#pragma unroll
            for (int mi = 0; mi < 2; mi++) {
                int r = wm + mi * 16 + gid;
                a[mi][0] = As[kb + tig][r];
                a[mi][1] = As[kb + tig][r + 8];
                a[mi][2] = As[kb + tig + 4][r];
                a[mi][3] = As[kb + tig + 4][r + 8];
            }
#pragma unroll
            for (int ni = 0; ni < 8; ni++) {
                int c = wn + ni * 8 + gid;
                uint32_t b0 = Bs[kb + tig][c];
                uint32_t b1 = Bs[kb + tig + 4][c];
                mma_tf32(acc[0][ni], a[0], b0, b1);
                mma_tf32(acc[1][ni], a[1], b0, b1);
            }
        }
        __syncthreads();
    }

#pragma unroll
    for (int mi = 0; mi < 2; mi++) {
        int r0 = m0 + wm + mi * 16 + gid;
#pragma unroll
        for (int ni = 0; ni < 8; ni++) {
            int col = n0 + wn + ni * 8 + tig * 2;
            float bb0 = bias[col], bb1 = bias[col + 1];
            int h = col >> 6, d = col & 63;
            {
                int m = r0, b = m >> 10, s = m & 1023;
                *(float2*)&Out[((b * Hc + h) * Sc + s) * HDc + d] =
                    make_float2(acc[mi][ni][0] + bb0, acc[mi][ni][1] + bb1);
            }
            {
                int m = r0 + 8, b = m >> 10, s = m & 1023;
                *(float2*)&Out[((b * Hc + h) * Sc + s) * HDc + d] =
                    make_float2(acc[mi][ni][2] + bb0, acc[mi][ni][3] + bb1);
            }
        }
    }
}

// ---------------------------------------------------------------------------
// TF32 scores: E = exp(Q K^T / 8) + row sums. Per (b,h): 1024x1024, K=64.
// grid: (8, 8, 64)
// ---------------------------------------------------------------------------
__global__ __launch_bounds__(256) void scores_kernel() {
    __shared__ uint32_t As[32][133];
    __shared__ uint32_t Bs[32][133];
    __shared__ float rs[128];
    const int t = threadIdx.x;
    const int lane = t & 31, warp = t >> 5;
    const int gid = lane >> 2, tig = lane & 3;
    const int wm = (warp & 3) * 32, wn = (warp >> 2) * 64;
    const int bh = blockIdx.z;
    const int m0 = blockIdx.y * 128, n0 = blockIdx.x * 128;
    const float* Qb = g_Q + bh * Sc * HDc;
    const float* Kb = g_K + bh * Sc * HDc;

    float acc[2][8][4];
#pragma unroll
    for (int mi = 0; mi < 2; mi++)
#pragma unroll
        for (int ni = 0; ni < 8; ni++)
#pragma unroll
            for (int j = 0; j < 4; j++) acc[mi][ni][j] = 0.f;

#pragma unroll
    for (int k0 = 0; k0 < HDc; k0 += 32) {
#pragma unroll
        for (int i = 0; i < 4; i++) {
            int idx = i * 256 + t;
            int row = idx >> 3, kq = (idx & 7) * 4;
            float4 va = *(const float4*)&Qb[(m0 + row) * HDc + k0 + kq];
            As[kq + 0][row] = f2tf32(va.x); As[kq + 1][row] = f2tf32(va.y);
            As[kq + 2][row] = f2tf32(va.z); As[kq + 3][row] = f2tf32(va.w);
            float4 vb = *(const float4*)&Kb[(n0 + row) * HDc + k0 + kq];
            Bs[kq + 0][row] = f2tf32(vb.x); Bs[kq + 1][row] = f2tf32(vb.y);
            Bs[kq + 2][row] = f2tf32(vb.z); Bs[kq + 3][row] = f2tf32(vb.w);
        }
        __syncthreads();
#pragma unroll
        for (int ks = 0; ks < 4; ks++) {
            int kb = ks * 8;
            uint32_t a[2][4];
#pragma unroll
            for (int mi = 0; mi < 2; mi++) {
                int r = wm + mi * 16 + gid;
                a[mi][0] = As[kb + tig][r];
                a[mi][1] = As[kb + tig][r + 8];
                a[mi][2] = As[kb + tig + 4][r];
                a[mi][3] = As[kb + tig + 4][r + 8];
            }
#pragma unroll
            for (int ni = 0; ni < 8; ni++) {
                int c = wn + ni * 8 + gid;
                uint32_t b0 = Bs[kb + tig][c];
                uint32_t b1 = Bs[kb + tig + 4][c];
                mma_tf32(acc[0][ni], a[0], b0, b1);
                mma_tf32(acc[1][ni], a[1], b0, b1);
            }
        }
        __syncthreads();
    }

    if (t < 128) rs[t] = 0.f;
    __syncthreads();

    float* Eb = g_E + bh * Sc * Sc;
#pragma unroll
    for (int mi = 0; mi < 2; mi++) {
        int r0 = wm + mi * 16 + gid;   // local row in [0,128)
        float rsum0 = 0.f, rsum1 = 0.f;
#pragma unroll
        for (int ni = 0; ni < 8; ni++) {
            int col = n0 + wn + ni * 8 + tig * 2;
            float e0 = __expf(acc[mi][ni][0] * 0.125f);
            float e1 = __expf(acc[mi][ni][1] * 0.125f);
            float e2 = __expf(acc[mi][ni][2] * 0.125f);
            float e3 = __expf(acc[mi][ni][3] * 0.125f);
            *(float2*)&Eb[(m0 + r0) * Sc + col]     = make_float2(e0, e1);
            *(float2*)&Eb[(m0 + r0 + 8) * Sc + col] = make_float2(e2, e3);
            rsum0 += e0 + e1;
            rsum1 += e2 + e3;
        }
        atomicAdd(&rs[r0], rsum0);
        atomicAdd(&rs[r0 + 8], rsum1);
    }
    __syncthreads();
    if (t < 128) atomicAdd(&g_rowsum[bh * Sc + m0 + t], rs[t]);
}

// ---------------------------------------------------------------------------
// Fused normalize + entanglement mix + probs write + ctx = P @ V  (fp32 FFMA;
// memory-bound stage). Per CTA: (b, head g, 128 q rows).
// grid: (8, 64), 256 threads
// ---------------------------------------------------------------------------
__global__ __launch_bounds__(256) void mixctx_kernel(float* __restrict__ Pout) {
    __shared__ float Ps[16][132];
    __shared__ float Vs[16][68];
    __shared__ float ivg[128];
    __shared__ float ivp[128];
    const int t = threadIdx.x;
    const int tx = t & 15, ty = t >> 4;
    const int bh = blockIdx.y;
    const int b = bh >> 4, g = bh & 15;
    const int q0 = blockIdx.x * 128;
    const int p = g_partner[g];
    const float w = g_pw[g];

    if (t < 128) {
        ivg[t] = 1.f / g_rowsum[(b * Hc + g) * Sc + q0 + t];
        ivp[t] = w / g_rowsum[(b * Hc + p) * Sc + q0 + t];
    }
    const float* Eg = g_E + (b * Hc + g) * Sc * Sc;
    const float* Ep = g_E + (b * Hc + p) * Sc * Sc;
    const float* Vb = g_V + (b * Hc + g) * Sc * HDc;
    float* Pg = Pout + (size_t)(b * Hc + g) * Sc * Sc;

    float acc[8][4];
#pragma unroll
    for (int i = 0; i < 8; i++)
#pragma unroll
        for (int j = 0; j < 4; j++) acc[i][j] = 0.f;

    __syncthreads();

    for (int kt = 0; kt < Sc; kt += 16) {
#pragma unroll
        for (int l = 0; l < 2; l++) {
            int f = t * 2 + l;
            int row = f >> 2, kq = (f & 3) * 4;
            int q = q0 + row;
            int k = kt + kq;
            float4 eg = *(const float4*)&Eg[q * Sc + k];
            float4 ep = *(const float4*)&Ep[q * Sc + k];
            float ig = ivg[row], ip = ivp[row];
            float4 pr = make_float4(eg.x * ig + ep.x * ip, eg.y * ig + ep.y * ip,
                                    eg.z * ig + ep.z * ip, eg.w * ig + ep.w * ip);
            *(float4*)&Pg[q * Sc + k] = pr;
            Ps[kq + 0][row] = pr.x; Ps[kq + 1][row] = pr.y;
            Ps[kq + 2][row] = pr.z; Ps[kq + 3][row] = pr.w;
        }
        {
            int row = t >> 4;
            int dq = (t & 15) * 4;
            *(float4*)&Vs[row][dq] = *(const float4*)&Vb[(kt + row) * HDc + dq];
        }
        __syncthreads();
#pragma unroll
        for (int kk = 0; kk < 16; kk++) {
            float4 a0 = *(const float4*)&Ps[kk][ty * 4];
            float4 a1 = *(const float4*)&Ps[kk][64 + ty * 4];
            float4 bv = *(const float4*)&Vs[kk][tx * 4];
            float av[8] = {a0.x, a0.y, a0.z, a0.w, a1.x, a1.y, a1.z, a1.w};
            float bb[4] = {bv.x, bv.y, bv.z, bv.w};
#pragma unroll
            for (int i = 0; i < 8; i++)
#pragma unroll
                for (int j = 0; j < 4; j++) acc[i][j] += av[i] * bb[j];
        }
        __syncthreads();
    }

#pragma unroll
    for (int i = 0; i < 8; i++) {
        int r = (i < 4) ? (ty * 4 + i) : (64 + ty * 4 + i - 4);
        float4 o = make_float4(acc[i][0], acc[i][1], acc[i][2], acc[i][3]);
        *(float4*)&g_ctx[((b * Hc + g) * Sc + q0 + r) * HDc + tx * 4] = o;
    }
}

// ---------------------------------------------------------------------------
// TF32 output projection: out[4096,1024] = ctx_flat @ Wo^T + bo
// grid: (8, 32)
// ---------------------------------------------------------------------------
__global__ __launch_bounds__(256) void gemm_tf32_out(
    const float* __restrict__ W, const float* __restrict__ bias,
    float* __restrict__ Out) {
    __shared__ uint32_t As[32][133];
    __shared__ uint32_t Bs[32][133];
    const int t = threadIdx.x;
    const int lane = t & 31, warp = t >> 5;
    const int gid = lane >> 2, tig = lane & 3;
    const int wm = (warp & 3) * 32, wn = (warp >> 2) * 64;
    const int m0 = blockIdx.y * 128, n0 = blockIdx.x * 128;

    float acc[2][8][4];
#pragma unroll
    for (int mi = 0; mi < 2; mi++)
#pragma unroll
        for (int ni = 0; ni < 8; ni++)
#pragma unroll
            for (int j = 0; j < 4; j++) acc[mi][ni][j] = 0.f;

    for (int k0 = 0; k0 < Ec; k0 += 32) {
#pragma unroll
        for (int i = 0; i < 4; i++) {
            int idx = i * 256 + t;
            int row = idx >> 3, kq = (idx & 7) * 4;
            int k = k0 + kq;
            int m = m0 + row, b = m >> 10, s = m & 1023;
            float4 va = *(const float4*)&g_ctx[((b * Hc + (k >> 6)) * Sc + s) * HDc + (k & 63)];
            As[kq + 0][row] = f2tf32(va.x); As[kq + 1][row] = f2tf32(va.y);
            As[kq + 2][row] = f2tf32(va.z); As[kq + 3][row] = f2tf32(va.w);
            float4 vb = *(const float4*)&W[(n0 + row) * Ec + k];
            Bs[kq + 0][row] = f2tf32(vb.x); Bs[kq + 1][row] = f2tf32(vb.y);
            Bs[kq + 2][row] = f2tf32(vb.z); Bs[kq + 3][row] = f2tf32(vb.w);
        }
        __syncthreads();
#pragma unroll
        for (int ks = 0; ks < 4; ks++) {
            int kb = ks * 8;
            uint32_t a[2][4];
#pragma unroll
            for (int mi = 0; mi < 2; mi++) {
                int r = wm + mi * 16 + gid;
                a[mi][0] = As[kb + tig][r];
                a[mi][1] = As[kb + tig][r + 8];
                a[mi][2] = As[kb + tig + 4][r];
                a[mi][3] = As[kb + tig + 4][r + 8];
            }
#pragma unroll
            for (int ni = 0; ni < 8; ni++) {
                int c = wn + ni * 8 + gid;
                uint32_t b0 = Bs[kb + tig][c];
                uint32_t b1 = Bs[kb + tig + 4][c];
                mma_tf32(acc[0][ni], a[0], b0, b1);
                mma_tf32(acc[1][ni], a[1], b0, b1);
            }
        }
        __syncthreads();
    }

#pragma unroll
    for (int mi = 0; mi < 2; mi++) {
        int r0 = m0 + wm + mi * 16 + gid;
#pragma unroll
        for (int ni = 0; ni < 8; ni++) {
            int col = n0 + wn + ni * 8 + tig * 2;
            float bb0 = bias[col], bb1 = bias[col + 1];
            *(float2*)&Out[r0 * Ec + col] =
                make_float2(acc[mi][ni][0] + bb0, acc[mi][ni][1] + bb1);
            *(float2*)&Out[(r0 + 8) * Ec + col] =
                make_float2(acc[mi][ni][2] + bb0, acc[mi][ni][3] + bb1);
        }
    }
}

// ---------------------------------------------------------------------------
extern "C" void kernel_launch(void* const* d_in, const int* in_sizes, int n_in,
                              void* d_out, int out_size) {
    const float* query    = (const float*)d_in[0];
    const float* key      = (const float*)d_in[1];
    const float* value    = (const float*)d_in[2];
    const float* Wq       = (const float*)d_in[3];
    const float* bq       = (const float*)d_in[4];
    const float* Wk       = (const float*)d_in[5];
    const float* bk       = (const float*)d_in[6];
    const float* Wv       = (const float*)d_in[7];
    const float* bv       = (const float*)d_in[8];
    const float* Wo       = (const float*)d_in[9];
    const float* bo       = (const float*)d_in[10];
    const float* phase    = (const float*)d_in[11];
    const float* hadamard = (const float*)d_in[12];
    const float* ent      = (const float*)d_in[13];

    float* out   = (float*)d_out;
    float* probs = out + OUT_OFF;

    init_misc_kernel<<<1, 256>>>(ent, hadamard, phase, bq, bk);
    zero_rowsum_kernel<<<(Bc * Hc * Sc) / 256, 256>>>();
    wtrans_kernel<<<dim3(Hc, 16), 256>>>(Wq, hadamard, phase, 0);
    wtrans_kernel<<<dim3(Hc, 16), 256>>>(Wk, hadamard, phase, 1);

    dim3 gp(Ec / 128, Mc / 128);
    gemm_tf32_proj<<<gp, 256>>>(query, nullptr, nullptr, 0);
    gemm_tf32_proj<<<gp, 256>>>(key, nullptr, nullptr, 1);
    gemm_tf32_proj<<<gp, 256>>>(value, Wv, bv, 2);

    scores_kernel<<<dim3(Sc / 128, Sc / 128, Bc * Hc), 256>>>();
    mixctx_kernel<<<dim3(Sc / 128, Bc * Hc), 256>>>(probs);
    gemm_tf32_out<<<gp, 256>>>(Wo, bo, out);
}

// round 5
// speedup vs baseline: 1.9683x; 1.1790x over previous
#include <cuda_runtime.h>
#include <cstdint>

// ---------------------------------------------------------------------------
// QuantumAttention: B=4, S=1024, E=1024, H=16, HD=64
// out  = [B,S,E]           -> d_out[0 .. 4194304)
// probs= [B,H,S,S] (mixed) -> d_out[4194304 .. 71303168)
// Round 4: pair-symmetric TF32 tensor-core mix+ctx (E read once, P@V on mma).
// ---------------------------------------------------------------------------

#define Bc 4
#define Sc 1024
#define Ec 1024
#define Hc 16
#define HDc 64
#define Mc (Bc * Sc)           // 4096
#define OUT_OFF (Bc * Sc * Ec) // 4194304

// Scratch (device globals: allocation-free per harness rules)
__device__ float g_Wq_eff[Ec * Ec];
__device__ float g_Wk_eff[Ec * Ec];
__device__ float g_bq_eff[Ec];
__device__ float g_bk_eff[Ec];
__device__ float g_Q[Bc * Hc * Sc * HDc];
__device__ float g_K[Bc * Hc * Sc * HDc];
__device__ float g_V[Bc * Hc * Sc * HDc];
__device__ float g_ctx[Bc * Hc * Sc * HDc];
__device__ float g_rowsum[Bc * Hc * Sc];
__device__ float g_E[Bc * Hc * Sc * Sc];   // 256 MB: exp(scores), pre-normalization
__device__ int   g_partner[Hc];
__device__ float g_pw[Hc];
__device__ int   g_pairA[Hc / 2];
__device__ int   g_pairB[Hc / 2];

// ---------------------------------------------------------------------------
// TF32 helpers
// ---------------------------------------------------------------------------
__device__ __forceinline__ uint32_t f2tf32(float x) {
    uint32_t r;
    asm("cvt.rna.tf32.f32 %0, %1;" : "=r"(r) : "f"(x));
    return r;
}

__device__ __forceinline__ void mma_tf32(float* c, const uint32_t* a,
                                         uint32_t b0, uint32_t b1) {
    asm volatile(
        "mma.sync.aligned.m16n8k8.row.col.f32.tf32.tf32.f32 "
        "{%0,%1,%2,%3}, {%4,%5,%6,%7}, {%8,%9}, {%0,%1,%2,%3};\n"
        : "+f"(c[0]), "+f"(c[1]), "+f"(c[2]), "+f"(c[3])
        : "r"(a[0]), "r"(a[1]), "r"(a[2]), "r"(a[3]), "r"(b0), "r"(b1));
}

// ---------------------------------------------------------------------------
// Small setup: entanglement partners/pairs + effective biases
// ---------------------------------------------------------------------------
__global__ void init_misc_kernel(const float* __restrict__ ent,
                                 const float* __restrict__ had,
                                 const float* __restrict__ phase,
                                 const float* __restrict__ bq,
                                 const float* __restrict__ bk) {
    int t = threadIdx.x;
    if (t < Hc) {
        int p = t; float w = 0.f;
        for (int h = 0; h < Hc; h++) {
            if (h != t && ent[h * Hc + t] != 0.f) { p = h; w = ent[h * Hc + t]; }
        }
        g_partner[t] = p;
        g_pw[t] = w;
    }
    __syncthreads();
    if (t == 0) {
        int c = 0;
        for (int g = 0; g < Hc; g++) {
            int p = g_partner[g];
            if (p > g) { g_pairA[c] = g; g_pairB[c] = p; c++; }
            else if (p == g) { g_pairA[c] = g; g_pairB[c] = g; c++; }  // degenerate
        }
    }
    for (int j = t; j < Ec; j += blockDim.x) {
        int h = j >> 6, e = j & 63;
        float aq = 0.f, ak = 0.f;
        for (int d = 0; d < HDc; d++) {
            float hv = had[d * HDc + e];
            aq += hv * bq[h * HDc + d];
            ak += hv * bk[h * HDc + d];
        }
        float c = cosf(phase[j]);
        g_bq_eff[j] = c * aq;
        g_bk_eff[j] = c * ak;
    }
}

__global__ void zero_rowsum_kernel() {
    int i = blockIdx.x * blockDim.x + threadIdx.x;
    if (i < Bc * Hc * Sc) g_rowsum[i] = 0.f;
}

// ---------------------------------------------------------------------------
// Weight transform: Weff[h*64+e, i] = cos(phase[h,e]) * sum_d had[d,e] * W[h*64+d, i]
// grid: (16, 16) = (h, 64-col chunk). 4e x 4i register tiling.
// ---------------------------------------------------------------------------
__global__ __launch_bounds__(256) void wtrans_kernel(const float* __restrict__ W,
                                                     const float* __restrict__ had,
                                                     const float* __restrict__ phase,
                                                     int which) {
    float* Weff = (which == 0) ? g_Wq_eff : g_Wk_eff;
    __shared__ float sH[HDc * 65];
    __shared__ float sW[HDc][68];
    __shared__ float sc[HDc];
    const int h = blockIdx.x;
    const int i0 = blockIdx.y * 64;
    const int t = threadIdx.x;
    for (int j = t; j < HDc * HDc; j += 256) {
        int d = j >> 6, e = j & 63;
        sH[d * 65 + e] = had[j];
    }
    if (t < HDc) sc[t] = cosf(phase[h * HDc + t]);
#pragma unroll
    for (int i = 0; i < 4; i++) {
        int idx = i * 256 + t;
        int d = idx >> 4, q = (idx & 15) * 4;
        *(float4*)&sW[d][q] = *(const float4*)&W[(h * HDc + d) * Ec + i0 + q];
    }
    __syncthreads();

    const int tx = t & 15;
    const int ty = t >> 4;
    float acc[4][4];
#pragma unroll
    for (int a = 0; a < 4; a++)
#pragma unroll
        for (int b = 0; b < 4; b++) acc[a][b] = 0.f;

#pragma unroll 8
    for (int d = 0; d < HDc; d++) {
        float4 w = *(const float4*)&sW[d][tx * 4];
#pragma unroll
        for (int ee = 0; ee < 4; ee++) {
            float hv = sH[d * 65 + ty * 4 + ee];
            acc[ee][0] += hv * w.x;
            acc[ee][1] += hv * w.y;
            acc[ee][2] += hv * w.z;
            acc[ee][3] += hv * w.w;
        }
    }
#pragma unroll
    for (int ee = 0; ee < 4; ee++) {
        int e = ty * 4 + ee;
        float s = sc[e];
        float4 o = make_float4(s * acc[ee][0], s * acc[ee][1],
                               s * acc[ee][2], s * acc[ee][3]);
        *(float4*)&Weff[(h * HDc + e) * Ec + i0 + tx * 4] = o;
    }
}

// ---------------------------------------------------------------------------
// TF32 projection GEMM: C[4096,1024] = A @ W^T + bias -> head layout [b,h,s,d]
// 128x128 CTA, k-tile 32, 8 warps (4m x 2n), mma m16n8k8. grid: (8, 32)
// ---------------------------------------------------------------------------
__global__ __launch_bounds__(256) void gemm_tf32_proj(
    const float* __restrict__ A, const float* __restrict__ Wraw,
    const float* __restrict__ braw, int which) {
    const float* W    = (which == 0) ? g_Wq_eff : (which == 1) ? g_Wk_eff : Wraw;
    const float* bias = (which == 0) ? g_bq_eff : (which == 1) ? g_bk_eff : braw;
    float* Out        = (which == 0) ? g_Q : (which == 1) ? g_K : g_V;

    __shared__ uint32_t As[32][133];
    __shared__ uint32_t Bs[32][133];
    const int t = threadIdx.x;
    const int lane = t & 31, warp = t >> 5;
    const int gid = lane >> 2, tig = lane & 3;
    const int wm = (warp & 3) * 32, wn = (warp >> 2) * 64;
    const int m0 = blockIdx.y * 128, n0 = blockIdx.x * 128;

    float acc[2][8][4];
#pragma unroll
    for (int mi = 0; mi < 2; mi++)
#pragma unroll
        for (int ni = 0; ni < 8; ni++)
#pragma unroll
            for (int j = 0; j < 4; j++) acc[mi][ni][j] = 0.f;

    for (int k0 = 0; k0 < Ec; k0 += 32) {
#pragma unroll
        for (int i = 0; i < 4; i++) {
            int idx = i * 256 + t;
            int row = idx >> 3, kq = (idx & 7) * 4;
            float4 va = *(const float4*)&A[(m0 + row) * Ec + k0 + kq];
            As[kq + 0][row] = f2tf32(va.x); As[kq + 1][row] = f2tf32(va.y);
            As[kq + 2][row] = f2tf32(va.z); As[kq + 3][row] = f2tf32(va.w);
            float4 vb = *(const float4*)&W[(n0 + row) * Ec + k0 + kq];
            Bs[kq + 0][row] = f2tf32(vb.x); Bs[kq + 1][row] = f2tf32(vb.y);
            Bs[kq + 2][row] = f2tf32(vb.z); Bs[kq + 3][row] = f2tf32(vb.w);
        }
        __syncthreads();
#pragma unroll
        for (int ks = 0; ks < 4; ks++) {
            int kb = ks * 8;
            uint32_t a[2][4];
#pragma unroll
            for (int mi = 0; mi < 2; mi++) {
                int r = wm + mi * 16 + gid;
                a[mi][0] = As[kb + tig][r];
                a[mi][1] = As[kb + tig][r + 8];
                a[mi][2] = As[kb + tig + 4][r];
                a[mi][3] = As[kb + tig + 4][r + 8];
            }
#pragma unroll
            for (int ni = 0; ni < 8; ni++) {
                int c = wn + ni * 8 + gid;
                uint32_t b0 = Bs[kb + tig][c];
                uint32_t b1 = Bs[kb + tig + 4][c];
                mma_tf32(acc[0][ni], a[0], b0, b1);
                mma_tf32(acc[1][ni], a[1], b0, b1);
            }
        }
        __syncthreads();
    }

#pragma unroll
    for (int mi = 0; mi < 2; mi++) {
        int r0 = m0 + wm + mi * 16 + gid;
#pragma unroll
        for (int ni = 0; ni < 8; ni++) {
            int col = n0 + wn + ni * 8 + tig * 2;
            float bb0 = bias[col], bb1 = bias[col + 1];
            int h = col >> 6, d = col & 63;
            {
                int m = r0, b = m >> 10, s = m & 1023;
                *(float2*)&Out[((b * Hc + h) * Sc + s) * HDc + d] =
                    make_float2(acc[mi][ni][0] + bb0, acc[mi][ni][1] + bb1);
            }
            {
                int m = r0 + 8, b = m >> 10, s = m & 1023;
                *(float2*)&Out[((b * Hc + h) * Sc + s) * HDc + d] =
                    make_float2(acc[mi][ni][2] + bb0, acc[mi][ni][3] + bb1);
            }
        }
    }
}

// ---------------------------------------------------------------------------
// TF32 scores: E = exp(Q K^T / 8) + row sums. Per (b,h): 1024x1024, K=64.
// grid: (8, 8, 64)
// ---------------------------------------------------------------------------
__global__ __launch_bounds__(256) void scores_kernel() {
    __shared__ uint32_t As[32][133];
    __shared__ uint32_t Bs[32][133];
    __shared__ float rs[128];
    const int t = threadIdx.x;
    const int lane = t & 31, warp = t >> 5;
    const int gid = lane >> 2, tig = lane & 3;
    const int wm = (warp & 3) * 32, wn = (warp >> 2) * 64;
    const int bh = blockIdx.z;
    const int m0 = blockIdx.y * 128, n0 = blockIdx.x * 128;
    const float* Qb = g_Q + bh * Sc * HDc;
    const float* Kb = g_K + bh * Sc * HDc;

    float acc[2][8][4];
#pragma unroll
    for (int mi = 0; mi < 2; mi++)
#pragma unroll
        for (int ni = 0; ni < 8; ni++)
#pragma unroll
            for (int j = 0; j < 4; j++) acc[mi][ni][j] = 0.f;

#pragma unroll
    for (int k0 = 0; k0 < HDc; k0 += 32) {
#pragma unroll
        for (int i = 0; i < 4; i++) {
            int idx = i * 256 + t;
            int row = idx >> 3, kq = (idx & 7) * 4;
            float4 va = *(const float4*)&Qb[(m0 + row) * HDc + k0 + kq];
            As[kq + 0][row] = f2tf32(va.x); As[kq + 1][row] = f2tf32(va.y);
            As[kq + 2][row] = f2tf32(va.z); As[kq + 3][row] = f2tf32(va.w);
            float4 vb = *(const float4*)&Kb[(n0 + row) * HDc + k0 + kq];
            Bs[kq + 0][row] = f2tf32(vb.x); Bs[kq + 1][row] = f2tf32(vb.y);
            Bs[kq + 2][row] = f2tf32(vb.z); Bs[kq + 3][row] = f2tf32(vb.w);
        }
        __syncthreads();
#pragma unroll
        for (int ks = 0; ks < 4; ks++) {
            int kb = ks * 8;
            uint32_t a[2][4];
#pragma unroll
            for (int mi = 0; mi < 2; mi++) {
                int r = wm + mi * 16 + gid;
                a[mi][0] = As[kb + tig][r];
                a[mi][1] = As[kb + tig][r + 8];
                a[mi][2] = As[kb + tig + 4][r];
                a[mi][3] = As[kb + tig + 4][r + 8];
            }
#pragma unroll
            for (int ni = 0; ni < 8; ni++) {
                int c = wn + ni * 8 + gid;
                uint32_t b0 = Bs[kb + tig][c];
                uint32_t b1 = Bs[kb + tig + 4][c];
                mma_tf32(acc[0][ni], a[0], b0, b1);
                mma_tf32(acc[1][ni], a[1], b0, b1);
            }
        }
        __syncthreads();
    }

    if (t < 128) rs[t] = 0.f;
    __syncthreads();

    float* Eb = g_E + (size_t)bh * Sc * Sc;
#pragma unroll
    for (int mi = 0; mi < 2; mi++) {
        int r0 = wm + mi * 16 + gid;   // local row in [0,128)
        float rsum0 = 0.f, rsum1 = 0.f;
#pragma unroll
        for (int ni = 0; ni < 8; ni++) {
            int col = n0 + wn + ni * 8 + tig * 2;
            float e0 = __expf(acc[mi][ni][0] * 0.125f);
            float e1 = __expf(acc[mi][ni][1] * 0.125f);
            float e2 = __expf(acc[mi][ni][2] * 0.125f);
            float e3 = __expf(acc[mi][ni][3] * 0.125f);
            *(float2*)&Eb[(m0 + r0) * Sc + col]     = make_float2(e0, e1);
            *(float2*)&Eb[(m0 + r0 + 8) * Sc + col] = make_float2(e2, e3);
            rsum0 += e0 + e1;
            rsum1 += e2 + e3;
        }
        atomicAdd(&rs[r0], rsum0);
        atomicAdd(&rs[r0 + 8], rsum1);
    }
    __syncthreads();
    if (t < 128) atomicAdd(&g_rowsum[bh * Sc + m0 + t], rs[t]);
}

// ---------------------------------------------------------------------------
// Pair-symmetric fused normalize + mix + probs write + ctx = P @ V (TF32 mma)
// One CTA = (batch b, head-pair (g,p), 128 q rows). Reads each E block once.
// Warps 0-3 compute ctx for head g, warps 4-7 for head p.
// grid: (8 qtiles, B*8 pairs) = (8, 32), 256 threads
// ---------------------------------------------------------------------------
__global__ __launch_bounds__(256) void mixctx_pair_kernel(float* __restrict__ Pout) {
    __shared__ uint32_t Ag[32][133];
    __shared__ uint32_t Ap[32][133];
    __shared__ uint32_t Vg[32][68];
    __shared__ uint32_t Vp[32][68];
    __shared__ float ivg[128], ivp[128], ivgw[128], ivpw[128];

    const int t = threadIdx.x;
    const int lane = t & 31, warp = t >> 5;
    const int gid = lane >> 2, tig = lane & 3;
    const int bp = blockIdx.y;
    const int b = bp >> 3, pr = bp & 7;
    const int g = g_pairA[pr], p = g_pairB[pr];
    const int q0 = blockIdx.x * 128;

    if (t < 128) {
        float rg = g_rowsum[(b * Hc + g) * Sc + q0 + t];
        float rp = g_rowsum[(b * Hc + p) * Sc + q0 + t];
        float w = g_pw[g];
        ivg[t] = 1.f / rg;          // probs_g <- Eg
        ivp[t] = 1.f / rp;          // probs_p <- Ep
        ivpw[t] = w / rp;           // probs_g <- Ep (partner contribution)
        ivgw[t] = w / rg;           // probs_p <- Eg
    }
    __syncthreads();

    const float* Eg = g_E + (size_t)(b * Hc + g) * Sc * Sc;
    const float* Ep = g_E + (size_t)(b * Hc + p) * Sc * Sc;
    const float* VgB = g_V + (size_t)(b * Hc + g) * Sc * HDc;
    const float* VpB = g_V + (size_t)(b * Hc + p) * Sc * HDc;
    float* Pg = Pout + (size_t)(b * Hc + g) * Sc * Sc;
    float* Pp = Pout + (size_t)(b * Hc + p) * Sc * Sc;

    float acc[2][8][4];
#pragma unroll
    for (int mi = 0; mi < 2; mi++)
#pragma unroll
        for (int ni = 0; ni < 8; ni++)
#pragma unroll
            for (int j = 0; j < 4; j++) acc[mi][ni][j] = 0.f;

    const int row = t >> 1;                 // 0..127
    const int kbase = (t & 1) * 16;         // 0 or 16
    const float vg1 = ivg[row], vpw = ivpw[row];
    const float vp1 = ivp[row], vgw = ivgw[row];

    for (int kt = 0; kt < Sc; kt += 32) {
        // ---- produce mixed probs chunk: gmem write + smem tf32 staging ----
        const float* EgR = Eg + (size_t)(q0 + row) * Sc + kt + kbase;
        const float* EpR = Ep + (size_t)(q0 + row) * Sc + kt + kbase;
        float* PgR = Pg + (size_t)(q0 + row) * Sc + kt + kbase;
        float* PpR = Pp + (size_t)(q0 + row) * Sc + kt + kbase;
#pragma unroll
        for (int i = 0; i < 4; i++) {
            float4 eg = *(const float4*)(EgR + i * 4);
            float4 ep = *(const float4*)(EpR + i * 4);
            float4 pg = make_float4(eg.x * vg1 + ep.x * vpw, eg.y * vg1 + ep.y * vpw,
                                    eg.z * vg1 + ep.z * vpw, eg.w * vg1 + ep.w * vpw);
            float4 pp = make_float4(ep.x * vp1 + eg.x * vgw, ep.y * vp1 + eg.y * vgw,
                                    ep.z * vp1 + eg.z * vgw, ep.w * vp1 + eg.w * vgw);
            *(float4*)(PgR + i * 4) = pg;
            *(float4*)(PpR + i * 4) = pp;
            int k = kbase + i * 4;
            Ag[k + 0][row] = f2tf32(pg.x); Ag[k + 1][row] = f2tf32(pg.y);
            Ag[k + 2][row] = f2tf32(pg.z); Ag[k + 3][row] = f2tf32(pg.w);
            Ap[k + 0][row] = f2tf32(pp.x); Ap[k + 1][row] = f2tf32(pp.y);
            Ap[k + 2][row] = f2tf32(pp.z); Ap[k + 3][row] = f2tf32(pp.w);
        }
        // ---- V chunks [32 k x 64 d] for both heads ----
#pragma unroll
        for (int i = 0; i < 2; i++) {
            int idx = i * 256 + t;
            int vr = idx >> 4, vc = (idx & 15) * 4;
            float4 vg = *(const float4*)&VgB[(kt + vr) * HDc + vc];
            Vg[vr][vc + 0] = f2tf32(vg.x); Vg[vr][vc + 1] = f2tf32(vg.y);
            Vg[vr][vc + 2] = f2tf32(vg.z); Vg[vr][vc + 3] = f2tf32(vg.w);
            float4 vp = *(const float4*)&VpB[(kt + vr) * HDc + vc];
            Vp[vr][vc + 0] = f2tf32(vp.x); Vp[vr][vc + 1] = f2tf32(vp.y);
            Vp[vr][vc + 2] = f2tf32(vp.z); Vp[vr][vc + 3] = f2tf32(vp.w);
        }
        __syncthreads();

        // ---- P @ V on tensor cores; warp 0-3: head g, warp 4-7: head p ----
        uint32_t (*As)[133] = (warp < 4) ? Ag : Ap;
        uint32_t (*Vs)[68]  = (warp < 4) ? Vg : Vp;
        const int wm = (warp & 3) * 32;
#pragma unroll
        for (int ks = 0; ks < 4; ks++) {
            int kb = ks * 8;
            uint32_t a[2][4];
#pragma unroll
            for (int mi = 0; mi < 2; mi++) {
                int r = wm + mi * 16 + gid;
                a[mi][0] = As[kb + tig][r];
                a[mi][1] = As[kb + tig][r + 8];
                a[mi][2] = As[kb + tig + 4][r];
                a[mi][3] = As[kb + tig + 4][r + 8];
            }
#pragma unroll
            for (int ni = 0; ni < 8; ni++) {
                int c = ni * 8 + gid;
                uint32_t b0 = Vs[kb + tig][c];
                uint32_t b1 = Vs[kb + tig + 4][c];
                mma_tf32(acc[0][ni], a[0], b0, b1);
                mma_tf32(acc[1][ni], a[1], b0, b1);
            }
        }
        __syncthreads();
    }

    // ---- epilogue: ctx[b, h, q0+.., :] ----
    const int h = (warp < 4) ? g : p;
    const int wm = (warp & 3) * 32;
    float* Cb = g_ctx + ((size_t)(b * Hc + h) * Sc + q0) * HDc;
#pragma unroll
    for (int mi = 0; mi < 2; mi++) {
        int r0 = wm + mi * 16 + gid;
#pragma unroll
        for (int ni = 0; ni < 8; ni++) {
            int col = ni * 8 + tig * 2;
            *(float2*)&Cb[r0 * HDc + col] =
                make_float2(acc[mi][ni][0], acc[mi][ni][1]);
            *(float2*)&Cb[(r0 + 8) * HDc + col] =
                make_float2(acc[mi][ni][2], acc[mi][ni][3]);
        }
    }
}

// ---------------------------------------------------------------------------
// TF32 output projection: out[4096,1024] = ctx_flat @ Wo^T + bo
// grid: (8, 32)
// ---------------------------------------------------------------------------
__global__ __launch_bounds__(256) void gemm_tf32_out(
    const float* __restrict__ W, const float* __restrict__ bias,
    float* __restrict__ Out) {
    __shared__ uint32_t As[32][133];
    __shared__ uint32_t Bs[32][133];
    const int t = threadIdx.x;
    const int lane = t & 31, warp = t >> 5;
    const int gid = lane >> 2, tig = lane & 3;
    const int wm = (warp & 3) * 32, wn = (warp >> 2) * 64;
    const int m0 = blockIdx.y * 128, n0 = blockIdx.x * 128;

    float acc[2][8][4];
#pragma unroll
    for (int mi = 0; mi < 2; mi++)
#pragma unroll
        for (int ni = 0; ni < 8; ni++)
#pragma unroll
            for (int j = 0; j < 4; j++) acc[mi][ni][j] = 0.f;

    for (int k0 = 0; k0 < Ec; k0 += 32) {
#pragma unroll
        for (int i = 0; i < 4; i++) {
            int idx = i * 256 + t;
            int row = idx >> 3, kq = (idx & 7) * 4;
            int k = k0 + kq;
            int m = m0 + row, b = m >> 10, s = m & 1023;
            float4 va = *(const float4*)&g_ctx[((b * Hc + (k >> 6)) * Sc + s) * HDc + (k & 63)];
            As[kq + 0][row] = f2tf32(va.x); As[kq + 1][row] = f2tf32(va.y);
            As[kq + 2][row] = f2tf32(va.z); As[kq + 3][row] = f2tf32(va.w);
            float4 vb = *(const float4*)&W[(n0 + row) * Ec + k];
            Bs[kq + 0][row] = f2tf32(vb.x); Bs[kq + 1][row] = f2tf32(vb.y);
            Bs[kq + 2][row] = f2tf32(vb.z); Bs[kq + 3][row] = f2tf32(vb.w);
        }
        __syncthreads();
#pragma unroll
        for (int ks = 0; ks < 4; ks++) {
            int kb = ks * 8;
            uint32_t a[2][4];
#pragma unroll
            for (int mi = 0; mi < 2; mi++) {
                int r = wm + mi * 16 + gid;
                a[mi][0] = As[kb + tig][r];
                a[mi][1] = As[kb + tig][r + 8];
                a[mi][2] = As[kb + tig + 4][r];
                a[mi][3] = As[kb + tig + 4][r + 8];
            }
#pragma unroll
            for (int ni = 0; ni < 8; ni++) {
                int c = wn + ni * 8 + gid;
                uint32_t b0 = Bs[kb + tig][c];
                uint32_t b1 = Bs[kb + tig + 4][c];
                mma_tf32(acc[0][ni], a[0], b0, b1);
                mma_tf32(acc[1][ni], a[1], b0, b1);
            }
        }
        __syncthreads();
    }

#pragma unroll
    for (int mi = 0; mi < 2; mi++) {
        int r0 = m0 + wm + mi * 16 + gid;
#pragma unroll
        for (int ni = 0; ni < 8; ni++) {
            int col = n0 + wn + ni * 8 + tig * 2;
            float bb0 = bias[col], bb1 = bias[col + 1];
            *(float2*)&Out[r0 * Ec + col] =
                make_float2(acc[mi][ni][0] + bb0, acc[mi][ni][1] + bb1);
            *(float2*)&Out[(r0 + 8) * Ec + col] =
                make_float2(acc[mi][ni][2] + bb0, acc[mi][ni][3] + bb1);
        }
    }
}

// ---------------------------------------------------------------------------
extern "C" void kernel_launch(void* const* d_in, const int* in_sizes, int n_in,
                              void* d_out, int out_size) {
    const float* query    = (const float*)d_in[0];
    const float* key      = (const float*)d_in[1];
    const float* value    = (const float*)d_in[2];
    const float* Wq       = (const float*)d_in[3];
    const float* bq       = (const float*)d_in[4];
    const float* Wk       = (const float*)d_in[5];
    const float* bk       = (const float*)d_in[6];
    const float* Wv       = (const float*)d_in[7];
    const float* bv       = (const float*)d_in[8];
    const float* Wo       = (const float*)d_in[9];
    const float* bo       = (const float*)d_in[10];
    const float* phase    = (const float*)d_in[11];
    const float* hadamard = (const float*)d_in[12];
    const float* ent      = (const float*)d_in[13];

    float* out   = (float*)d_out;
    float* probs = out + OUT_OFF;

    init_misc_kernel<<<1, 256>>>(ent, hadamard, phase, bq, bk);
    zero_rowsum_kernel<<<(Bc * Hc * Sc) / 256, 256>>>();
    wtrans_kernel<<<dim3(Hc, 16), 256>>>(Wq, hadamard, phase, 0);
    wtrans_kernel<<<dim3(Hc, 16), 256>>>(Wk, hadamard, phase, 1);

    dim3 gp(Ec / 128, Mc / 128);
    gemm_tf32_proj<<<gp, 256>>>(query, nullptr, nullptr, 0);
    gemm_tf32_proj<<<gp, 256>>>(key, nullptr, nullptr, 1);
    gemm_tf32_proj<<<gp, 256>>>(value, Wv, bv, 2);

    scores_kernel<<<dim3(Sc / 128, Sc / 128, Bc * Hc), 256>>>();
    mixctx_pair_kernel<<<dim3(Sc / 128, Bc * 8), 256>>>(probs);
    gemm_tf32_out<<<gp, 256>>>(Wo, bo, out);
}